// round 2
// baseline (speedup 1.0000x reference)
#include <cuda_runtime.h>
#include <cstdint>

#define N_BATCH 8
#define NN      2048
#define DF      128
#define NF      128
#define A_ELEMS (N_BATCH * NN * NN)   /* 33554432 */
#define H_OFF   A_ELEMS
#define ROWTILES 32                   /* kernel-1 row tiles (2048/64) */

// ---------------- scratch (no allocations allowed) ----------------
__device__ float g_dpart[ROWTILES * N_BATCH * NN];  // partial column sums [rt][b*NN+col]
__device__ float g_dr[N_BATCH * NN];                // rsqrt(1 + colsum)
__device__ float g_Xs[N_BATCH * NN * DF];           // dr[j] * X[j,:]
__device__ float g_DADH[N_BATCH * NN * DF];         // first GEMM result

// ---------------- f32x2 packed-FMA helpers ----------------
__device__ __forceinline__ void ffma2(unsigned long long& d,
                                      unsigned long long a,
                                      unsigned long long b) {
    asm("fma.rn.f32x2 %0, %1, %2, %0;" : "+l"(d) : "l"(a), "l"(b));
}
__device__ __forceinline__ unsigned long long pack2(float lo, float hi) {
    unsigned long long r;
    asm("mov.b64 %0, {%1, %2};" : "=l"(r) : "f"(lo), "f"(hi));
    return r;
}
__device__ __forceinline__ float2 unpack2(unsigned long long v) {
    float2 r;
    asm("mov.b64 {%0, %1}, %2;" : "=f"(r.x), "=f"(r.y) : "l"(v));
    return r;
}

// ============================================================================
// Kernel 1: copy A -> out AND accumulate per-block partial column sums.
// Grid (ROWTILES=32, N_BATCH=8), 512 threads. Each block: 64 rows x 2048 cols.
// Thread t owns columns [4t, 4t+4) via float4. Deterministic (no atomics).
// ============================================================================
__global__ void __launch_bounds__(512) colsum_copy_kernel(
    const float* __restrict__ A, float* __restrict__ out)
{
    const int rt = blockIdx.x;            // 0..31
    const int b  = blockIdx.y;            // 0..7
    const int t  = threadIdx.x;           // 0..511
    const size_t base = (size_t)b * NN * NN + (size_t)rt * 64 * NN;
    const float4* A4 = (const float4*)(A + base);
    float4*       O4 = (float4*)(out + base);

    float4 acc = make_float4(0.f, 0.f, 0.f, 0.f);
#pragma unroll 8
    for (int r = 0; r < 64; r++) {
        float4 v = A4[r * (NN / 4) + t];
        O4[r * (NN / 4) + t] = v;
        acc.x += v.x; acc.y += v.y; acc.z += v.z; acc.w += v.w;
    }
    float4* P4 = (float4*)(g_dpart + (size_t)rt * (N_BATCH * NN) + (size_t)b * NN);
    P4[t] = acc;
}

// ============================================================================
// Kernel 2: dr = rsqrt(1 + colsum); Xs[j,:] = dr[j] * X[j,:].
// Grid 16384 (one block per (b,node)), 128 threads (one per feature).
// ============================================================================
__global__ void __launch_bounds__(128) finalize_kernel(const float* __restrict__ X)
{
    const int col = blockIdx.x;           // b*NN + j
    const int t   = threadIdx.x;          // feature
    float s = 1.0f;                       // +1 from the identity (self-loop)
#pragma unroll
    for (int rt = 0; rt < ROWTILES; rt++)
        s += g_dpart[rt * (N_BATCH * NN) + col];
    s = rsqrtf(s);
    if (t == 0) g_dr[col] = s;
    g_Xs[(size_t)col * DF + t] = s * X[(size_t)col * DF + t];
}

// ============================================================================
// Kernel 3: DADH = dr[i] * (A @ Xs + Xs[i,:])   per batch.
// Tile: 64 (M) x 128 (all features), 128 threads, 8x8 micro-tile, K-tile 16.
// f32x2 packed FMA: acc pairs along the feature dim.
// Grid (32 m-tiles, 8 batches).
// ============================================================================
__global__ void __launch_bounds__(128) gemm1_kernel(const float* __restrict__ A)
{
    __shared__ float Ast[16][68];     // A tile transposed [k][m], padded stride
    __shared__ float Xss[16][128];    // Xs tile [k][f]

    const int b  = blockIdx.y;
    const int i0 = blockIdx.x * 64;
    const int t  = threadIdx.x;
    const int tm = t >> 4;            // 0..7  (8 rows each)
    const int tn = t & 15;            // 0..15 (8 features each)

    const float* Ab = A + (size_t)b * NN * NN;
    const float* Xb = g_Xs + (size_t)b * NN * DF;

    unsigned long long acc[8][4];
#pragma unroll
    for (int m = 0; m < 8; m++)
#pragma unroll
        for (int p = 0; p < 4; p++) acc[m][p] = 0ULL;   // (0.f, 0.f)

    for (int kt = 0; kt < NN; kt += 16) {
        // ---- stage A tile (transposed) ----
#pragma unroll
        for (int i = 0; i < 8; i++) {
            int idx = t + i * 128;            // 0..1023
            int m = idx >> 4, k = idx & 15;
            Ast[k][m] = Ab[(size_t)(i0 + m) * NN + kt + k];
        }
        // ---- stage Xs tile (float4, coalesced) ----
        const float4* X4 = (const float4*)(Xb + (size_t)kt * DF);
#pragma unroll
        for (int i = 0; i < 4; i++) {
            int idx = t + i * 128;            // 0..511
            int r = idx >> 5, c = idx & 31;
            ((float4*)Xss[r])[c] = X4[r * 32 + c];
        }
        __syncthreads();

#pragma unroll
        for (int kk = 0; kk < 16; kk++) {
            float4 a0 = *(const float4*)&Ast[kk][tm * 8];
            float4 a1 = *(const float4*)&Ast[kk][tm * 8 + 4];
            const ulonglong2* xr = (const ulonglong2*)&Xss[kk][tn * 8];
            ulonglong2 xq0 = xr[0];
            ulonglong2 xq1 = xr[1];
            unsigned long long ad[8];
            ad[0] = pack2(a0.x, a0.x); ad[1] = pack2(a0.y, a0.y);
            ad[2] = pack2(a0.z, a0.z); ad[3] = pack2(a0.w, a0.w);
            ad[4] = pack2(a1.x, a1.x); ad[5] = pack2(a1.y, a1.y);
            ad[6] = pack2(a1.z, a1.z); ad[7] = pack2(a1.w, a1.w);
#pragma unroll
            for (int m = 0; m < 8; m++) {
                ffma2(acc[m][0], ad[m], xq0.x);
                ffma2(acc[m][1], ad[m], xq0.y);
                ffma2(acc[m][2], ad[m], xq1.x);
                ffma2(acc[m][3], ad[m], xq1.y);
            }
        }
        __syncthreads();
    }

    // ---- epilogue: DADH = dr[i] * (acc + Xs[i,:]) ----
#pragma unroll
    for (int m = 0; m < 8; m++) {
        int i = i0 + tm * 8 + m;
        float s = g_dr[b * NN + i];
        const float2* Xrow = (const float2*)(Xb + (size_t)i * DF);
        float2*       Drow = (float2*)(g_DADH + ((size_t)b * NN + i) * DF);
#pragma unroll
        for (int p = 0; p < 4; p++) {
            float2 v  = unpack2(acc[m][p]);
            int    f2 = tn * 4 + p;
            float2 xs = Xrow[f2];
            float2 o;
            o.x = s * (v.x + xs.x);
            o.y = s * (v.y + xs.y);
            Drow[f2] = o;
        }
    }
}

// ============================================================================
// Kernel 4: H = relu(DADH @ W), batches flattened: [16384,128] @ [128,128].
// Same tiling as gemm1, K = 128 (8 k-tiles). Grid 256 blocks.
// ============================================================================
__global__ void __launch_bounds__(128) gemm2_kernel(
    const float* __restrict__ W, float* __restrict__ out)
{
    __shared__ float Dst[16][68];
    __shared__ float Ws[16][128];

    const int i0 = blockIdx.x * 64;   // row tile in flattened [16384] dim
    const int t  = threadIdx.x;
    const int tm = t >> 4;
    const int tn = t & 15;

    unsigned long long acc[8][4];
#pragma unroll
    for (int m = 0; m < 8; m++)
#pragma unroll
        for (int p = 0; p < 4; p++) acc[m][p] = 0ULL;

    for (int kt = 0; kt < DF; kt += 16) {
#pragma unroll
        for (int i = 0; i < 8; i++) {
            int idx = t + i * 128;
            int m = idx >> 4, k = idx & 15;
            Dst[k][m] = g_DADH[(size_t)(i0 + m) * DF + kt + k];
        }
        const float4* W4 = (const float4*)(W + (size_t)kt * NF);
#pragma unroll
        for (int i = 0; i < 4; i++) {
            int idx = t + i * 128;
            int r = idx >> 5, c = idx & 31;
            ((float4*)Ws[r])[c] = W4[r * 32 + c];
        }
        __syncthreads();

#pragma unroll
        for (int kk = 0; kk < 16; kk++) {
            float4 a0 = *(const float4*)&Dst[kk][tm * 8];
            float4 a1 = *(const float4*)&Dst[kk][tm * 8 + 4];
            const ulonglong2* wr = (const ulonglong2*)&Ws[kk][tn * 8];
            ulonglong2 wq0 = wr[0];
            ulonglong2 wq1 = wr[1];
            unsigned long long ad[8];
            ad[0] = pack2(a0.x, a0.x); ad[1] = pack2(a0.y, a0.y);
            ad[2] = pack2(a0.z, a0.z); ad[3] = pack2(a0.w, a0.w);
            ad[4] = pack2(a1.x, a1.x); ad[5] = pack2(a1.y, a1.y);
            ad[6] = pack2(a1.z, a1.z); ad[7] = pack2(a1.w, a1.w);
#pragma unroll
            for (int m = 0; m < 8; m++) {
                ffma2(acc[m][0], ad[m], wq0.x);
                ffma2(acc[m][1], ad[m], wq0.y);
                ffma2(acc[m][2], ad[m], wq1.x);
                ffma2(acc[m][3], ad[m], wq1.y);
            }
        }
        __syncthreads();
    }

    // ---- epilogue: relu, write H after the A copy ----
#pragma unroll
    for (int m = 0; m < 8; m++) {
        int i = i0 + tm * 8 + m;
        float2* Orow = (float2*)(out + H_OFF + (size_t)i * NF);
#pragma unroll
        for (int p = 0; p < 4; p++) {
            float2 v = unpack2(acc[m][p]);
            float2 o;
            o.x = fmaxf(v.x, 0.f);
            o.y = fmaxf(v.y, 0.f);
            Orow[tn * 4 + p] = o;
        }
    }
}

// ============================================================================
extern "C" void kernel_launch(void* const* d_in, const int* in_sizes, int n_in,
                              void* d_out, int out_size)
{
    const float* A = (const float*)d_in[0];   // [8,2048,2048]
    const float* X = (const float*)d_in[1];   // [8,2048,128]
    const float* W = (const float*)d_in[2];   // [128,128]
    float* out = (float*)d_out;               // [A | H]

    colsum_copy_kernel<<<dim3(ROWTILES, N_BATCH), 512>>>(A, out);
    finalize_kernel<<<N_BATCH * NN, 128>>>(X);
    gemm1_kernel<<<dim3(NN / 64, N_BATCH), 128>>>(A);
    gemm2_kernel<<<N_BATCH * NN / 64, 128>>>(W, out);
}

// round 7
// speedup vs baseline: 2.1873x; 2.1873x over previous
#include <cuda_runtime.h>
#include <cuda_bf16.h>
#include <cstdint>

#define N_BATCH 8
#define NN      2048
#define DF      128
#define NF      128
#define A_ELEMS (N_BATCH * NN * NN)   /* 33554432 */
#define H_OFF   A_ELEMS
#define ROWTILES 32

// ---------------- scratch (no allocations allowed) ----------------
__device__ float g_dpart[ROWTILES * N_BATCH * NN];
__device__ float g_dr[N_BATCH * NN];
__device__ float          g_Xs   [N_BATCH * NN * DF];  // dr[j]*X[j,:]  (f32, epilogue)
__device__ __nv_bfloat16  g_Xsh  [N_BATCH * NN * DF];  // hi part (B operand)
__device__ __nv_bfloat16  g_Xsl  [N_BATCH * NN * DF];  // lo part
__device__ __nv_bfloat16  g_Dhi  [N_BATCH * NN * DF];  // gemm1 result hi
__device__ __nv_bfloat16  g_Dlo  [N_BATCH * NN * DF];  // gemm1 result lo
__device__ __nv_bfloat16  g_Whi[DF * NF];
__device__ __nv_bfloat16  g_Wlo[DF * NF];

// ---------------- helpers ----------------
__device__ __forceinline__ uint32_t smem_u32(const void* p) {
    uint32_t a;
    asm("{ .reg .u64 t; cvta.to.shared.u64 t, %1; cvt.u32.u64 %0, t; }" : "=r"(a) : "l"(p));
    return a;
}
__device__ __forceinline__ uint32_t bf2_bits(__nv_bfloat162 h) {
    return *reinterpret_cast<uint32_t*>(&h);
}
// split f32x4 -> hi/lo bf16x4 (packed as uint2 each)
__device__ __forceinline__ void split4(float4 v, uint2& whi, uint2& wlo) {
    __nv_bfloat162 h01 = __floats2bfloat162_rn(v.x, v.y);
    __nv_bfloat162 h23 = __floats2bfloat162_rn(v.z, v.w);
    float2 f01 = __bfloat1622float2(h01);
    float2 f23 = __bfloat1622float2(h23);
    __nv_bfloat162 l01 = __floats2bfloat162_rn(v.x - f01.x, v.y - f01.y);
    __nv_bfloat162 l23 = __floats2bfloat162_rn(v.z - f23.x, v.w - f23.y);
    whi.x = bf2_bits(h01); whi.y = bf2_bits(h23);
    wlo.x = bf2_bits(l01); wlo.y = bf2_bits(l23);
}

#define LDSM4(r, a)                                                          \
    asm volatile("ldmatrix.sync.aligned.m8n8.x4.shared.b16 {%0,%1,%2,%3}, [%4];" \
        : "=r"((r)[0]), "=r"((r)[1]), "=r"((r)[2]), "=r"((r)[3]) : "r"(a))
#define LDSM4T(r, a)                                                         \
    asm volatile("ldmatrix.sync.aligned.m8n8.x4.trans.shared.b16 {%0,%1,%2,%3}, [%4];" \
        : "=r"((r)[0]), "=r"((r)[1]), "=r"((r)[2]), "=r"((r)[3]) : "r"(a))
#define MMA16816(d, a, b0, b1)                                               \
    asm volatile("mma.sync.aligned.m16n8k16.row.col.f32.bf16.bf16.f32 "      \
        "{%0,%1,%2,%3},{%4,%5,%6,%7},{%8,%9},{%0,%1,%2,%3};"                 \
        : "+f"((d)[0]), "+f"((d)[1]), "+f"((d)[2]), "+f"((d)[3])             \
        : "r"((a)[0]), "r"((a)[1]), "r"((a)[2]), "r"((a)[3]), "r"(b0), "r"(b1))

// ============================================================================
// Kernel 1: copy A -> out AND per-block partial column sums (deterministic).
// ============================================================================
__global__ void __launch_bounds__(512) colsum_copy_kernel(
    const float* __restrict__ A, float* __restrict__ out)
{
    const int rt = blockIdx.x, b = blockIdx.y, t = threadIdx.x;
    const size_t base = (size_t)b * NN * NN + (size_t)rt * 64 * NN;
    const float4* A4 = (const float4*)(A + base);
    float4*       O4 = (float4*)(out + base);

    float4 acc = make_float4(0.f, 0.f, 0.f, 0.f);
#pragma unroll 8
    for (int r = 0; r < 64; r++) {
        float4 v = A4[r * (NN / 4) + t];
        O4[r * (NN / 4) + t] = v;
        acc.x += v.x; acc.y += v.y; acc.z += v.z; acc.w += v.w;
    }
    ((float4*)(g_dpart + (size_t)rt * (N_BATCH * NN) + (size_t)b * NN))[t] = acc;
}

// ============================================================================
// Kernel 2: dr = rsqrt(1 + colsum); Xs = dr[j]*X[j,:]  (f32 + bf16 hi/lo)
// ============================================================================
__global__ void __launch_bounds__(128) finalize_kernel(const float* __restrict__ X)
{
    const int col = blockIdx.x;
    const int t   = threadIdx.x;
    float s = 1.0f;
#pragma unroll
    for (int rt = 0; rt < ROWTILES; rt++)
        s += g_dpart[rt * (N_BATCH * NN) + col];
    s = rsqrtf(s);
    if (t == 0) g_dr[col] = s;
    float v = s * X[(size_t)col * DF + t];
    g_Xs[(size_t)col * DF + t] = v;
    __nv_bfloat16 hi = __float2bfloat16_rn(v);
    g_Xsh[(size_t)col * DF + t] = hi;
    g_Xsl[(size_t)col * DF + t] = __float2bfloat16_rn(v - __bfloat162float(hi));
}

// ============================================================================
// Kernel 2b: W -> bf16 hi/lo
// ============================================================================
__global__ void __launch_bounds__(256) convw_kernel(const float* __restrict__ W)
{
    int i = blockIdx.x * 256 + threadIdx.x;
    float v = W[i];
    __nv_bfloat16 hi = __float2bfloat16_rn(v);
    g_Whi[i] = hi;
    g_Wlo[i] = __float2bfloat16_rn(v - __bfloat162float(hi));
}

// ============================================================================
// Kernel 3: gemm1, split-bf16 3-MMA (Ahi*Bhi + Ahi*Blo + Alo*Bhi).
// Tile 128x128, K-chunk 32, 256 threads (8 warps: 4M x 2N), double buffered.
// ============================================================================
#define BK      32
#define NCH     (NN / BK)                 /* 64 */
#define PA_B    80                        /* A tile row stride, bytes */
#define PB_B    272                       /* B tile row stride, bytes */
#define SZ_A    (128 * PA_B)              /* 10240 */
#define SZ_B    (BK * PB_B)               /* 8704  */
#define STG     (2 * SZ_A + 2 * SZ_B)     /* per-stage: Ahi,Alo,Bhi,Blo = 37888 */
#define SM1_TOT (2 * STG)                 /* 75776 */

__global__ void __launch_bounds__(256) gemm1_mma_kernel(const float* __restrict__ A)
{
    extern __shared__ __align__(16) char sm[];

    const int t = threadIdx.x;
    const int lane = t & 31, wid = t >> 5;
    const int wm = wid & 3, wn = wid >> 2;      // warp tile: 32 M x 64 N
    const int b = blockIdx.y, i0 = blockIdx.x * 128;

    const float* Ab = A + (size_t)b * NN * NN + (size_t)i0 * NN;
    const __nv_bfloat16* Bhi = g_Xsh + (size_t)b * NN * DF;
    const __nv_bfloat16* Blo = g_Xsl + (size_t)b * NN * DF;

    const uint32_t sbase = smem_u32(sm);
    const int lrow  = lane & 15;
    const int lcol8 = (lane >> 4) * 8;

    float acc[2][8][4];
#pragma unroll
    for (int mi = 0; mi < 2; mi++)
#pragma unroll
        for (int ni = 0; ni < 8; ni++)
#pragma unroll
            for (int q = 0; q < 4; q++) acc[mi][ni][q] = 0.f;

    // ---- stage chunk 0 directly ----
    {
#pragma unroll
        for (int i = 0; i < 4; i++) {
            int idx = t + i * 256, row = idx >> 3, c4 = idx & 7;
            float4 v = *(const float4*)(Ab + (size_t)row * NN + c4 * 4);
            uint2 whi, wlo; split4(v, whi, wlo);
            *(uint2*)(sm + row * PA_B + c4 * 8)        = whi;
            *(uint2*)(sm + SZ_A + row * PA_B + c4 * 8) = wlo;
        }
#pragma unroll
        for (int i = 0; i < 2; i++) {
            int idx = t + i * 256, row = idx >> 4, cc = idx & 15;
            *(uint4*)(sm + 2 * SZ_A + row * PB_B + cc * 16) =
                *(const uint4*)(Bhi + (size_t)row * DF + cc * 8);
            *(uint4*)(sm + 2 * SZ_A + SZ_B + row * PB_B + cc * 16) =
                *(const uint4*)(Blo + (size_t)row * DF + cc * 8);
        }
    }
    __syncthreads();

    float4 ra[4];
    uint4  rbh[2], rbl[2];

    for (int c = 0; c < NCH; c++) {
        const int st = c & 1;
        if (c + 1 < NCH) {
            const float* Asrc = Ab + (c + 1) * BK;
#pragma unroll
            for (int i = 0; i < 4; i++) {
                int idx = t + i * 256, row = idx >> 3, c4 = idx & 7;
                ra[i] = *(const float4*)(Asrc + (size_t)row * NN + c4 * 4);
            }
            const size_t boff = (size_t)(c + 1) * BK * DF;
#pragma unroll
            for (int i = 0; i < 2; i++) {
                int idx = t + i * 256, row = idx >> 4, cc = idx & 15;
                rbh[i] = *(const uint4*)(Bhi + boff + (size_t)row * DF + cc * 8);
                rbl[i] = *(const uint4*)(Blo + boff + (size_t)row * DF + cc * 8);
            }
        }
        // ---- compute on stage st ----
        const uint32_t sAh = sbase + st * STG;
        const uint32_t sAl = sAh + SZ_A;
        const uint32_t sBh = sAh + 2 * SZ_A;
        const uint32_t sBl = sBh + SZ_B;
#pragma unroll
        for (int ks = 0; ks < 2; ks++) {
            uint32_t ah[2][4], al[2][4], bh[4][4], bl[4][4];
            const uint32_t arow = (wm * 32 + lrow) * PA_B + (ks * 16 + lcol8) * 2;
#pragma unroll
            for (int mi = 0; mi < 2; mi++) {
                LDSM4(ah[mi], sAh + arow + mi * 16 * PA_B);
                LDSM4(al[mi], sAl + arow + mi * 16 * PA_B);
            }
            const uint32_t brow = (ks * 16 + lrow) * PB_B + (wn * 64 + lcol8) * 2;
#pragma unroll
            for (int ni = 0; ni < 4; ni++) {
                LDSM4T(bh[ni], sBh + brow + ni * 32);
                LDSM4T(bl[ni], sBl + brow + ni * 32);
            }
#pragma unroll
            for (int mi = 0; mi < 2; mi++)
#pragma unroll
                for (int ni = 0; ni < 4; ni++) {
                    MMA16816(acc[mi][ni * 2],     ah[mi], bh[ni][0], bh[ni][1]);
                    MMA16816(acc[mi][ni * 2 + 1], ah[mi], bh[ni][2], bh[ni][3]);
                    MMA16816(acc[mi][ni * 2],     ah[mi], bl[ni][0], bl[ni][1]);
                    MMA16816(acc[mi][ni * 2 + 1], ah[mi], bl[ni][2], bl[ni][3]);
                    MMA16816(acc[mi][ni * 2],     al[mi], bh[ni][0], bh[ni][1]);
                    MMA16816(acc[mi][ni * 2 + 1], al[mi], bh[ni][2], bh[ni][3]);
                }
        }
        // ---- store staged chunk c+1 ----
        if (c + 1 < NCH) {
            const int ns = (c + 1) & 1;
            char* dst = sm + ns * STG;
#pragma unroll
            for (int i = 0; i < 4; i++) {
                int idx = t + i * 256, row = idx >> 3, c4 = idx & 7;
                uint2 whi, wlo; split4(ra[i], whi, wlo);
                *(uint2*)(dst + row * PA_B + c4 * 8)        = whi;
                *(uint2*)(dst + SZ_A + row * PA_B + c4 * 8) = wlo;
            }
#pragma unroll
            for (int i = 0; i < 2; i++) {
                int idx = t + i * 256, row = idx >> 4, cc = idx & 15;
                *(uint4*)(dst + 2 * SZ_A + row * PB_B + cc * 16)        = rbh[i];
                *(uint4*)(dst + 2 * SZ_A + SZ_B + row * PB_B + cc * 16) = rbl[i];
            }
        }
        __syncthreads();
    }

    // ---- epilogue: v = dr[i]*(acc + Xs[i,:]) -> hi/lo bf16 pair ----
    const int g  = lane >> 2, tg = lane & 3;
#pragma unroll
    for (int mi = 0; mi < 2; mi++) {
#pragma unroll
        for (int rr = 0; rr < 2; rr++) {
            int r = i0 + wm * 32 + mi * 16 + g + rr * 8;
            float s = g_dr[b * NN + r];
            const float* Xrow = g_Xs + ((size_t)b * NN + r) * DF;
            __nv_bfloat162* DHrow = (__nv_bfloat162*)(g_Dhi + ((size_t)b * NN + r) * DF);
            __nv_bfloat162* DLrow = (__nv_bfloat162*)(g_Dlo + ((size_t)b * NN + r) * DF);
#pragma unroll
            for (int ni = 0; ni < 8; ni++) {
                int cb = wn * 64 + ni * 8 + tg * 2;
                float2 x = *(const float2*)(Xrow + cb);
                float v0 = s * (acc[mi][ni][rr * 2 + 0] + x.x);
                float v1 = s * (acc[mi][ni][rr * 2 + 1] + x.y);
                __nv_bfloat162 h = __floats2bfloat162_rn(v0, v1);
                float2 hf = __bfloat1622float2(h);
                DHrow[cb >> 1] = h;
                DLrow[cb >> 1] = __floats2bfloat162_rn(v0 - hf.x, v1 - hf.y);
            }
        }
    }
}

// ============================================================================
// Kernel 4: H = relu(DADH @ W), split-bf16 3-MMA, K=128 single stage.
// Tiles: Dhi/Dlo [128][128] + Whi/Wlo [128][128], stride 272B each.
// ============================================================================
#define G2_SZ   (128 * 272)                /* 34816 per tile */
#define SM2_TOT (4 * G2_SZ)                /* 139264 */

__global__ void __launch_bounds__(256) gemm2_mma_kernel(float* __restrict__ out)
{
    extern __shared__ __align__(16) char sm2[];

    const int t = threadIdx.x;
    const int lane = t & 31, wid = t >> 5;
    const int wm = wid & 3, wn = wid >> 2;
    const int i0 = blockIdx.x * 128;

    const uint32_t sbase = smem_u32(sm2);
    const int lrow  = lane & 15;
    const int lcol8 = (lane >> 4) * 8;

#pragma unroll
    for (int i = 0; i < 8; i++) {
        int idx = t + i * 256, row = idx >> 4, cc = idx & 15;
        size_t go = (size_t)(i0 + row) * DF + cc * 8;
        *(uint4*)(sm2 + row * 272 + cc * 16)          = *(const uint4*)(g_Dhi + go);
        *(uint4*)(sm2 + G2_SZ + row * 272 + cc * 16)  = *(const uint4*)(g_Dlo + go);
        size_t wo = (size_t)row * NF + cc * 8;
        *(uint4*)(sm2 + 2 * G2_SZ + row * 272 + cc * 16) = *(const uint4*)(g_Whi + wo);
        *(uint4*)(sm2 + 3 * G2_SZ + row * 272 + cc * 16) = *(const uint4*)(g_Wlo + wo);
    }
    __syncthreads();

    float acc[2][8][4];
#pragma unroll
    for (int mi = 0; mi < 2; mi++)
#pragma unroll
        for (int ni = 0; ni < 8; ni++)
#pragma unroll
            for (int q = 0; q < 4; q++) acc[mi][ni][q] = 0.f;

#pragma unroll
    for (int ks = 0; ks < 8; ks++) {
        uint32_t ah[2][4], al[2][4], bh[4][4], bl[4][4];
        const uint32_t arow = (wm * 32 + lrow) * 272 + (ks * 16 + lcol8) * 2;
#pragma unroll
        for (int mi = 0; mi < 2; mi++) {
            LDSM4(ah[mi], sbase + arow + mi * 16 * 272);
            LDSM4(al[mi], sbase + G2_SZ + arow + mi * 16 * 272);
        }
        const uint32_t brow = (ks * 16 + lrow) * 272 + (wn * 64 + lcol8) * 2;
#pragma unroll
        for (int ni = 0; ni < 4; ni++) {
            LDSM4T(bh[ni], sbase + 2 * G2_SZ + brow + ni * 32);
            LDSM4T(bl[ni], sbase + 3 * G2_SZ + brow + ni * 32);
        }
#pragma unroll
        for (int mi = 0; mi < 2; mi++)
#pragma unroll
            for (int ni = 0; ni < 4; ni++) {
                MMA16816(acc[mi][ni * 2],     ah[mi], bh[ni][0], bh[ni][1]);
                MMA16816(acc[mi][ni * 2 + 1], ah[mi], bh[ni][2], bh[ni][3]);
                MMA16816(acc[mi][ni * 2],     ah[mi], bl[ni][0], bl[ni][1]);
                MMA16816(acc[mi][ni * 2 + 1], ah[mi], bl[ni][2], bl[ni][3]);
                MMA16816(acc[mi][ni * 2],     al[mi], bh[ni][0], bh[ni][1]);
                MMA16816(acc[mi][ni * 2 + 1], al[mi], bh[ni][2], bh[ni][3]);
            }
    }

    const int g  = lane >> 2, tg = lane & 3;
#pragma unroll
    for (int mi = 0; mi < 2; mi++) {
#pragma unroll
        for (int rr = 0; rr < 2; rr++) {
            int r = i0 + wm * 32 + mi * 16 + g + rr * 8;
            float2* Orow = (float2*)(out + H_OFF + (size_t)r * NF);
#pragma unroll
            for (int ni = 0; ni < 8; ni++) {
                int cb = wn * 64 + ni * 8 + tg * 2;
                float2 o;
                o.x = fmaxf(acc[mi][ni][rr * 2 + 0], 0.f);
                o.y = fmaxf(acc[mi][ni][rr * 2 + 1], 0.f);
                Orow[cb >> 1] = o;
            }
        }
    }
}

// ============================================================================
extern "C" void kernel_launch(void* const* d_in, const int* in_sizes, int n_in,
                              void* d_out, int out_size)
{
    const float* A = (const float*)d_in[0];
    const float* X = (const float*)d_in[1];
    const float* W = (const float*)d_in[2];
    float* out = (float*)d_out;

    cudaFuncSetAttribute(gemm1_mma_kernel,
                         cudaFuncAttributeMaxDynamicSharedMemorySize, SM1_TOT);
    cudaFuncSetAttribute(gemm2_mma_kernel,
                         cudaFuncAttributeMaxDynamicSharedMemorySize, SM2_TOT);

    colsum_copy_kernel<<<dim3(ROWTILES, N_BATCH), 512>>>(A, out);
    finalize_kernel<<<N_BATCH * NN, 128>>>(X);
    convw_kernel<<<DF * NF / 256, 256>>>(W);
    gemm1_mma_kernel<<<dim3(NN / 128, N_BATCH), 256, SM1_TOT>>>(A);
    gemm2_mma_kernel<<<N_BATCH * NN / 128, 256, SM2_TOT>>>(out);
}